// round 10
// baseline (speedup 1.0000x reference)
#include <cuda_runtime.h>
#include <cuda_bf16.h>
#include <cstdint>

// Problem constants
#define B_   64
#define L_   4096
#define KD_  128
#define H_   4
#define OUT_ 256

#define CHUNKS 16                // L-chunks per batch (pass 1)
#define WARPS  4                 // warps per block in pass 1 (128 threads)
#define ROWS_PER_WARP (L_ / CHUNKS / WARPS)   // 64 rows = two 32-row halves
#define NBLK1 (B_ * CHUNKS)      // 1024

// Deterministic scratch (no device allocation allowed)
__device__ float g_pacc[NBLK1][KD_ * H_];   // 1024 x 512 f32 = 2 MB
__device__ float g_pZ[NBLK1][H_];
__device__ float g_pooled[B_][KD_ * H_];    // normalized pooled vectors

__device__ __forceinline__ float warp_sum32(float v) {
#pragma unroll
    for (int off = 16; off >= 1; off >>= 1)
        v += __shfl_xor_sync(0xffffffffu, v, off);
    return v;
}

// Pop up to 4 set bits from a 32-bit mask; returns slot-liveness mask.
__device__ __forceinline__ unsigned extract4(unsigned& m, int r[4]) {
    unsigned live = 0;
    r[0] = 0;
#pragma unroll
    for (int i = 0; i < 4; i++) {
        if (m) {
            r[i] = __ffs(m) - 1;
            m &= m - 1;
            live |= 1u << i;
        } else {
            r[i] = r[0];               // padded duplicate, zero-weighted
        }
    }
    return live;
}

// 8-value butterfly transpose-reduce. In: wv[0..7] per lane. Out: wv[0] on
// lane l == full 32-lane sum of value (l & 7). Folds {4,2,1} put value (l&7)
// summed over the lane's 8-lane subgroup; shfl(8)+shfl(16) complete all 32.
__device__ __forceinline__ float butterfly8(float wv[8], int lane) {
#pragma unroll
    for (int step = 0; step < 3; step++) {
        const int off = 4 >> step;
        const bool up = (lane & off) != 0;
#pragma unroll
        for (int i = 0; i < 4; i++) {
            if (i < (4 >> step)) {
                const float send = up ? wv[i] : wv[i + (4 >> step)];
                const float recv = __shfl_xor_sync(0xffffffffu, send, off);
                wv[i] = (up ? wv[i + (4 >> step)] : wv[i]) + recv;
            }
        }
    }
    float s = wv[0];
    s += __shfl_xor_sync(0xffffffffu, s, 8);
    s += __shfl_xor_sync(0xffffffffu, s, 16);
    return s;
}

// ---------------------------------------------------------------------------
// Pass 1. Warp owns 64 rows as two 32-bit mask bitmaps; live rows processed
// 4 per iteration. Scores computed as TWO 8-value batches (4 rows x head-pair)
// so only 8 temp registers are live at once -> <=64 regs -> occupancy 8
// blocks/SM -> the whole 1024-block grid is ONE wave (this was R9's limiter:
// 80 regs -> occ 6 -> 1.15 waves, 15% tail at near-zero utilization).
// After butterfly8, lane l holds the score of value (l&7) = (row (l&7)>>1,
// head (l&1) [+2 for batch B]). One __expf per lane per batch.
// exp(-1e9)==0 in fp32 => skipping masked rows is exact; |score|<~4 => no
// max subtraction needed.
// ---------------------------------------------------------------------------
__global__ void __launch_bounds__(128, 8)
pool_pass1(const float* __restrict__ x,
           const int* __restrict__ mask,   // bool coerced to int32 by harness
           const float* __restrict__ q)
{
    const int blk  = blockIdx.x;
    const int b    = blk / CHUNKS;
    const int c    = blk % CHUNKS;
    const int w    = threadIdx.x >> 5;
    const int lane = threadIdx.x & 31;

    __shared__ float sP[WARPS][2][16];      // double-buffered weight broadcast
    __shared__ float sAcc[WARPS][KD_ * H_];
    __shared__ float sZ[WARPS][H_];

    float4 q4[H_];
#pragma unroll
    for (int h = 0; h < H_; h++)
        q4[h] = *reinterpret_cast<const float4*>(q + h * KD_ + lane * 4);

    float acc[4][H_];
#pragma unroll
    for (int j = 0; j < 4; j++)
#pragma unroll
        for (int h = 0; h < H_; h++) acc[j][h] = 0.0f;
    float zaccA = 0.0f, zaccB = 0.0f;

    const int l0 = c * (L_ / CHUNKS) + w * ROWS_PER_WARP;
    const float* xb = x + (size_t)b * L_ * KD_ + (size_t)l0 * KD_;
    const int* mb = mask + (size_t)b * L_ + l0;

    int pb = 0;
#pragma unroll 1
    for (int half = 0; half < 2; half++) {
        unsigned m = __ballot_sync(0xffffffffu, mb[half * 32 + lane] != 0);
        const char* baseL = (const char*)(xb + (size_t)half * 32 * KD_) + lane * 16;

        while (m) {
            int r[4];
            const unsigned live = extract4(m, r);

            float4 xv[4];
#pragma unroll
            for (int i = 0; i < 4; i++)
                xv[i] = *reinterpret_cast<const float4*>(baseL + ((unsigned)r[i] << 9));

            const unsigned myrow = (lane & 7) >> 1;   // row slot this lane ends with
            const float keep = ((live >> myrow) & 1u) ? 1.0f : 0.0f;

            // ---- batch A: heads 0,1 -> wv[row*2 + hh] ----
            float wv[8];
#pragma unroll
            for (int i = 0; i < 4; i++) {
                wv[i * 2 + 0] = xv[i].x * q4[0].x + xv[i].y * q4[0].y
                              + xv[i].z * q4[0].z + xv[i].w * q4[0].w;
                wv[i * 2 + 1] = xv[i].x * q4[1].x + xv[i].y * q4[1].y
                              + xv[i].z * q4[1].z + xv[i].w * q4[1].w;
            }
            float eA = __expf(butterfly8(wv, lane)) * keep;

            // ---- batch B: heads 2,3 ----
#pragma unroll
            for (int i = 0; i < 4; i++) {
                wv[i * 2 + 0] = xv[i].x * q4[2].x + xv[i].y * q4[2].y
                              + xv[i].z * q4[2].z + xv[i].w * q4[2].w;
                wv[i * 2 + 1] = xv[i].x * q4[3].x + xv[i].y * q4[3].y
                              + xv[i].z * q4[3].z + xv[i].w * q4[3].w;
            }
            float eB = __expf(butterfly8(wv, lane)) * keep;

            // ---- broadcast weights: lanes 0..7 carry the distinct values ----
            if (lane < 8) {
                const int row = lane >> 1, hh = lane & 1;
                sP[w][pb][row * 4 + hh]     = eA;   // heads 0,1
                sP[w][pb][row * 4 + 2 + hh] = eB;   // heads 2,3
            } else {
                eA = 0.0f; eB = 0.0f;
            }
            __syncwarp();
            zaccA += eA;                    // Z[lane&1]   partial
            zaccB += eB;                    // Z[2+(lane&1)] partial

            // ---- accumulate 4 rows ----
#pragma unroll
            for (int i = 0; i < 4; i++) {
                const float4 pv = *reinterpret_cast<const float4*>(&sP[w][pb][i * 4]);
                acc[0][0] = fmaf(xv[i].x, pv.x, acc[0][0]);
                acc[0][1] = fmaf(xv[i].x, pv.y, acc[0][1]);
                acc[0][2] = fmaf(xv[i].x, pv.z, acc[0][2]);
                acc[0][3] = fmaf(xv[i].x, pv.w, acc[0][3]);
                acc[1][0] = fmaf(xv[i].y, pv.x, acc[1][0]);
                acc[1][1] = fmaf(xv[i].y, pv.y, acc[1][1]);
                acc[1][2] = fmaf(xv[i].y, pv.z, acc[1][2]);
                acc[1][3] = fmaf(xv[i].y, pv.w, acc[1][3]);
                acc[2][0] = fmaf(xv[i].z, pv.x, acc[2][0]);
                acc[2][1] = fmaf(xv[i].z, pv.y, acc[2][1]);
                acc[2][2] = fmaf(xv[i].z, pv.z, acc[2][2]);
                acc[2][3] = fmaf(xv[i].z, pv.w, acc[2][3]);
                acc[3][0] = fmaf(xv[i].w, pv.x, acc[3][0]);
                acc[3][1] = fmaf(xv[i].w, pv.y, acc[3][1]);
                acc[3][2] = fmaf(xv[i].w, pv.z, acc[3][2]);
                acc[3][3] = fmaf(xv[i].w, pv.w, acc[3][3]);
            }
            pb ^= 1;                       // next iter writes other buffer; its
                                           // syncwarp fences reuse of this one.
        }
    }

    // Z: zaccA lanes hold head (lane&1); reduce over same-parity lanes.
    float zA = zaccA, zB = zaccB;
#pragma unroll
    for (int off = 16; off >= 2; off >>= 1) {
        zA += __shfl_xor_sync(0xffffffffu, zA, off);
        zB += __shfl_xor_sync(0xffffffffu, zB, off);
    }
    // lanes 0,1 hold Z[0],Z[1] (zA) and Z[2],Z[3] (zB)

    // ---- block-level deterministic reduce ----
#pragma unroll
    for (int j = 0; j < 4; j++)
#pragma unroll
        for (int h = 0; h < H_; h++)
            sAcc[w][(lane * 4 + j) * H_ + h] = acc[j][h];   // idx = k*H + h
    if (lane < 2) {
        sZ[w][lane]     = zA;
        sZ[w][2 + lane] = zB;
    }
    __syncthreads();

    for (int idx = threadIdx.x; idx < KD_ * H_; idx += 128) {
        float vv = 0.f;
#pragma unroll
        for (int ww = 0; ww < WARPS; ww++) vv += sAcc[ww][idx];
        g_pacc[blk][idx] = vv;
    }
    if (threadIdx.x < H_) {
        float vv = 0.f;
#pragma unroll
        for (int ww = 0; ww < WARPS; ww++) vv += sZ[ww][threadIdx.x];
        g_pZ[blk][threadIdx.x] = vv;
    }
}

// ---------------------------------------------------------------------------
// Pass 2a: combine chunk partials + normalize -> g_pooled[b][*].
// ---------------------------------------------------------------------------
__global__ void __launch_bounds__(512, 2)
pool_combine()
{
    const int b   = blockIdx.x;
    const int tid = threadIdx.x;
    __shared__ float Zs[H_];

    if (tid < H_) {
        float vv = 0.f;
#pragma unroll
        for (int c = 0; c < CHUNKS; c++) vv += g_pZ[b * CHUNKS + c][tid];
        Zs[tid] = vv;
    }
    float vv = 0.f;
#pragma unroll
    for (int c = 0; c < CHUNKS; c++) vv += g_pacc[b * CHUNKS + c][tid];
    __syncthreads();
    g_pooled[b][tid] = vv / Zs[tid & (H_ - 1)];
}

// ---------------------------------------------------------------------------
// Pass 2b: out = relu(pooled @ W^T + b + relu(emb[num])).
// ---------------------------------------------------------------------------
__global__ void __launch_bounds__(256, 4)
pool_gemv(const float* __restrict__ W,
          const float* __restrict__ bias,
          const float* __restrict__ emb,
          const int* __restrict__ num,
          float* __restrict__ out)
{
    const int b    = blockIdx.x >> 3;
    const int og   = blockIdx.x & 7;
    const int tid  = threadIdx.x;
    const int wrp  = tid >> 5;
    const int lane = tid & 31;
    const int o0   = og * 32 + wrp * 4;

    __shared__ float pooled[KD_ * H_];
    for (int idx = tid; idx < (KD_ * H_) / 4; idx += 256)
        reinterpret_cast<float4*>(pooled)[idx] =
            reinterpret_cast<const float4*>(g_pooled[b])[idx];
    __syncthreads();

    float4 pv[4];
#pragma unroll
    for (int qi = 0; qi < 4; qi++)
        pv[qi] = *reinterpret_cast<const float4*>(&pooled[qi * 128 + lane * 4]);

    float a[4];
#pragma unroll
    for (int j = 0; j < 4; j++) {
        const float* Wr = W + (size_t)(o0 + j) * (KD_ * H_);
        float ssum = 0.f;
#pragma unroll
        for (int qi = 0; qi < 4; qi++) {
            const float4 wv = *reinterpret_cast<const float4*>(Wr + qi * 128 + lane * 4);
            ssum = fmaf(wv.x, pv[qi].x, fmaf(wv.y, pv[qi].y,
                   fmaf(wv.z, pv[qi].z, fmaf(wv.w, pv[qi].w, ssum))));
        }
        a[j] = warp_sum32(ssum);
    }

    if (lane == 0) {
        const int nb = num[b];
#pragma unroll
        for (int j = 0; j < 4; j++) {
            const int o = o0 + j;
            float vv = a[j] + bias[o] + fmaxf(emb[(size_t)nb * OUT_ + o], 0.f);
            out[(size_t)b * OUT_ + o] = fmaxf(vv, 0.f);
        }
    }
}

// ---------------------------------------------------------------------------
// Launch.  Inputs (metadata order): x, mask, num, queries, W, b, emb
// ---------------------------------------------------------------------------
extern "C" void kernel_launch(void* const* d_in, const int* in_sizes, int n_in,
                              void* d_out, int out_size)
{
    const float* x    = (const float*)d_in[0];
    const int*   mask = (const int*)d_in[1];     // bool -> int32 on upload
    const int*   num  = (const int*)d_in[2];
    const float* q    = (const float*)d_in[3];
    const float* W    = (const float*)d_in[4];
    const float* bias = (const float*)d_in[5];
    const float* emb  = (const float*)d_in[6];
    float*       out  = (float*)d_out;

    pool_pass1<<<NBLK1, 128>>>(x, mask, q);
    pool_combine<<<B_, 512>>>();
    pool_gemv<<<B_ * 8, 256>>>(W, bias, emb, num, out);
}

// round 11
// speedup vs baseline: 1.0012x; 1.0012x over previous
#include <cuda_runtime.h>
#include <cuda_bf16.h>
#include <cstdint>

// Problem constants
#define B_   64
#define L_   4096
#define KD_  128
#define H_   4
#define OUT_ 256

#define CHUNKS 16                // L-chunks per batch (pass 1)
#define WARPS  4                 // warps per block in pass 1 (128 threads)
#define ROWS_PER_WARP (L_ / CHUNKS / WARPS)   // 64 rows = two 32-row halves
#define NBLK1 (B_ * CHUNKS)      // 1024

// Deterministic scratch (no device allocation allowed)
__device__ float g_pacc[NBLK1][KD_ * H_];   // 1024 x 512 f32 = 2 MB
__device__ float g_pZ[NBLK1][H_];
__device__ float g_pooled[B_][KD_ * H_];    // normalized pooled vectors

__device__ __forceinline__ float warp_sum32(float v) {
#pragma unroll
    for (int off = 16; off >= 1; off >>= 1)
        v += __shfl_xor_sync(0xffffffffu, v, off);
    return v;
}

// Pop up to 4 set bits from a 32-bit mask; returns slot-liveness mask.
__device__ __forceinline__ unsigned extract4(unsigned& m, int r[4]) {
    unsigned live = 0;
    r[0] = 0;
#pragma unroll
    for (int i = 0; i < 4; i++) {
        if (m) {
            r[i] = __ffs(m) - 1;
            m &= m - 1;
            live |= 1u << i;
        } else {
            r[i] = r[0];               // padded duplicate, zero-weighted
        }
    }
    return live;
}

// 8-value butterfly transpose-reduce. In: wv[0..7] per lane. Out: return on
// lane l == full 32-lane sum of value (l & 7). Folds {4,2,1} reduce within
// 8-lane subgroups; shfl(8)+shfl(16) complete all 32 lanes.
__device__ __forceinline__ float butterfly8(float wv[8], int lane) {
#pragma unroll
    for (int step = 0; step < 3; step++) {
        const int off = 4 >> step;
        const bool up = (lane & off) != 0;
#pragma unroll
        for (int i = 0; i < 4; i++) {
            if (i < (4 >> step)) {
                const float send = up ? wv[i] : wv[i + (4 >> step)];
                const float recv = __shfl_xor_sync(0xffffffffu, send, off);
                wv[i] = (up ? wv[i + (4 >> step)] : wv[i]) + recv;
            }
        }
    }
    float s = wv[0];
    s += __shfl_xor_sync(0xffffffffu, s, 8);
    s += __shfl_xor_sync(0xffffffffu, s, 16);
    return s;
}

// ---------------------------------------------------------------------------
// Pass 1. Same algorithm as R10 (proven correct), restructured to fit 64
// registers WITHOUT spills (R10 profile: regs=64 = clamped from a natural 80
// -> spill LDL/STL in the hot loop; measured issues/row ~110 vs ~46 static):
//   - q4 lives in shared memory (qS), reloaded per iteration (4 LDS.128).
//   - xv is staged through per-warp smem (xS): both head-pair dots run first,
//     then xv is stored and its registers die before the butterflies; the
//     accumulate re-reads it via LDS.128 (per-lane same-address => ordered by
//     program order, no sync needed).
// exp(-1e9)==0 in fp32 => skipping masked rows is exact; |score|<~4 => no
// max subtraction needed.
// ---------------------------------------------------------------------------
__global__ void __launch_bounds__(128, 8)
pool_pass1(const float* __restrict__ x,
           const int* __restrict__ mask,   // bool coerced to int32 by harness
           const float* __restrict__ q)
{
    const int blk  = blockIdx.x;
    const int b    = blk / CHUNKS;
    const int c    = blk % CHUNKS;
    const int w    = threadIdx.x >> 5;
    const int lane = threadIdx.x & 31;

    __shared__ float4 qS[H_][32];           // query chunks, lane-strided
    __shared__ float4 xS[WARPS][4][32];     // staged x rows (per warp)
    __shared__ float  sP[WARPS][2][16];     // double-buffered weight broadcast
    __shared__ float  sAcc[WARPS][KD_ * H_];
    __shared__ float  sZ[WARPS][H_];

    // qS[h][lane] = floats [lane*4, lane*4+4) of head h's query
    qS[w][lane] = *reinterpret_cast<const float4*>(q + w * KD_ + lane * 4);
    __syncthreads();

    float acc[4][H_];
#pragma unroll
    for (int j = 0; j < 4; j++)
#pragma unroll
        for (int h = 0; h < H_; h++) acc[j][h] = 0.0f;
    float zaccA = 0.0f, zaccB = 0.0f;

    const int l0 = c * (L_ / CHUNKS) + w * ROWS_PER_WARP;
    const float* xb = x + (size_t)b * L_ * KD_ + (size_t)l0 * KD_;
    const int* mb = mask + (size_t)b * L_ + l0;

    int pb = 0;
#pragma unroll 1
    for (int half = 0; half < 2; half++) {
        unsigned m = __ballot_sync(0xffffffffu, mb[half * 32 + lane] != 0);
        const char* baseL = (const char*)(xb + (size_t)half * 32 * KD_) + lane * 16;

        while (m) {
            int r[4];
            const unsigned live = extract4(m, r);

            const unsigned myrow = (lane & 7) >> 1;
            const float keep = ((live >> myrow) & 1u) ? 1.0f : 0.0f;

            // ---- load 4 rows; both head-pair dots; stage xv to smem ----
            float wvA[8], wvB[8];
            {
                const float4 qa = qS[0][lane], qb = qS[1][lane];
                const float4 qc = qS[2][lane], qd = qS[3][lane];
#pragma unroll
                for (int i = 0; i < 4; i++) {
                    const float4 xv = *reinterpret_cast<const float4*>(
                        baseL + ((unsigned)r[i] << 9));
                    wvA[i * 2 + 0] = xv.x * qa.x + xv.y * qa.y + xv.z * qa.z + xv.w * qa.w;
                    wvA[i * 2 + 1] = xv.x * qb.x + xv.y * qb.y + xv.z * qb.z + xv.w * qb.w;
                    wvB[i * 2 + 0] = xv.x * qc.x + xv.y * qc.y + xv.z * qc.z + xv.w * qc.w;
                    wvB[i * 2 + 1] = xv.x * qd.x + xv.y * qd.y + xv.z * qd.z + xv.w * qd.w;
                    xS[w][i][lane] = xv;    // xv registers die here
                }
            }

            // ---- butterflies + softmax weights ----
            float eA = __expf(butterfly8(wvA, lane)) * keep;
            float eB = __expf(butterfly8(wvB, lane)) * keep;

            // lanes 0..7 carry the distinct values
            if (lane < 8) {
                const int row = lane >> 1, hh = lane & 1;
                sP[w][pb][row * 4 + hh]     = eA;   // heads 0,1
                sP[w][pb][row * 4 + 2 + hh] = eB;   // heads 2,3
            } else {
                eA = 0.0f; eB = 0.0f;
            }
            __syncwarp();
            zaccA += eA;                    // Z[lane&1]     partial
            zaccB += eB;                    // Z[2+(lane&1)] partial

            // ---- accumulate 4 rows (x re-read from smem stage) ----
#pragma unroll
            for (int i = 0; i < 4; i++) {
                const float4 xr = xS[w][i][lane];
                const float4 pv = *reinterpret_cast<const float4*>(&sP[w][pb][i * 4]);
                acc[0][0] = fmaf(xr.x, pv.x, acc[0][0]);
                acc[0][1] = fmaf(xr.x, pv.y, acc[0][1]);
                acc[0][2] = fmaf(xr.x, pv.z, acc[0][2]);
                acc[0][3] = fmaf(xr.x, pv.w, acc[0][3]);
                acc[1][0] = fmaf(xr.y, pv.x, acc[1][0]);
                acc[1][1] = fmaf(xr.y, pv.y, acc[1][1]);
                acc[1][2] = fmaf(xr.y, pv.z, acc[1][2]);
                acc[1][3] = fmaf(xr.y, pv.w, acc[1][3]);
                acc[2][0] = fmaf(xr.z, pv.x, acc[2][0]);
                acc[2][1] = fmaf(xr.z, pv.y, acc[2][1]);
                acc[2][2] = fmaf(xr.z, pv.z, acc[2][2]);
                acc[2][3] = fmaf(xr.z, pv.w, acc[2][3]);
                acc[3][0] = fmaf(xr.w, pv.x, acc[3][0]);
                acc[3][1] = fmaf(xr.w, pv.y, acc[3][1]);
                acc[3][2] = fmaf(xr.w, pv.z, acc[3][2]);
                acc[3][3] = fmaf(xr.w, pv.w, acc[3][3]);
            }
            pb ^= 1;                       // next iter writes other sP buffer;
                                           // its syncwarp fences reuse. xS is
                                           // per-lane same-address -> ordered.
        }
    }

    // Z reduce: same-parity lanes -> lanes 0,1 hold (Z0,Z1) and (Z2,Z3)
    float zA = zaccA, zB = zaccB;
#pragma unroll
    for (int off = 16; off >= 2; off >>= 1) {
        zA += __shfl_xor_sync(0xffffffffu, zA, off);
        zB += __shfl_xor_sync(0xffffffffu, zB, off);
    }

    // ---- block-level deterministic reduce ----
#pragma unroll
    for (int j = 0; j < 4; j++)
#pragma unroll
        for (int h = 0; h < H_; h++)
            sAcc[w][(lane * 4 + j) * H_ + h] = acc[j][h];   // idx = k*H + h
    if (lane < 2) {
        sZ[w][lane]     = zA;
        sZ[w][2 + lane] = zB;
    }
    __syncthreads();

    for (int idx = threadIdx.x; idx < KD_ * H_; idx += 128) {
        float vv = 0.f;
#pragma unroll
        for (int ww = 0; ww < WARPS; ww++) vv += sAcc[ww][idx];
        g_pacc[blk][idx] = vv;
    }
    if (threadIdx.x < H_) {
        float vv = 0.f;
#pragma unroll
        for (int ww = 0; ww < WARPS; ww++) vv += sZ[ww][threadIdx.x];
        g_pZ[blk][threadIdx.x] = vv;
    }
}

// ---------------------------------------------------------------------------
// Pass 2a: combine chunk partials + normalize -> g_pooled[b][*].
// ---------------------------------------------------------------------------
__global__ void __launch_bounds__(512, 2)
pool_combine()
{
    const int b   = blockIdx.x;
    const int tid = threadIdx.x;
    __shared__ float Zs[H_];

    if (tid < H_) {
        float vv = 0.f;
#pragma unroll
        for (int c = 0; c < CHUNKS; c++) vv += g_pZ[b * CHUNKS + c][tid];
        Zs[tid] = vv;
    }
    float vv = 0.f;
#pragma unroll
    for (int c = 0; c < CHUNKS; c++) vv += g_pacc[b * CHUNKS + c][tid];
    __syncthreads();
    g_pooled[b][tid] = vv / Zs[tid & (H_ - 1)];
}

// ---------------------------------------------------------------------------
// Pass 2b: out = relu(pooled @ W^T + b + relu(emb[num])).
// ---------------------------------------------------------------------------
__global__ void __launch_bounds__(256, 4)
pool_gemv(const float* __restrict__ W,
          const float* __restrict__ bias,
          const float* __restrict__ emb,
          const int* __restrict__ num,
          float* __restrict__ out)
{
    const int b    = blockIdx.x >> 3;
    const int og   = blockIdx.x & 7;
    const int tid  = threadIdx.x;
    const int wrp  = tid >> 5;
    const int lane = tid & 31;
    const int o0   = og * 32 + wrp * 4;

    __shared__ float pooled[KD_ * H_];
    for (int idx = tid; idx < (KD_ * H_) / 4; idx += 256)
        reinterpret_cast<float4*>(pooled)[idx] =
            reinterpret_cast<const float4*>(g_pooled[b])[idx];
    __syncthreads();

    float4 pv[4];
#pragma unroll
    for (int qi = 0; qi < 4; qi++)
        pv[qi] = *reinterpret_cast<const float4*>(&pooled[qi * 128 + lane * 4]);

    float a[4];
#pragma unroll
    for (int j = 0; j < 4; j++) {
        const float* Wr = W + (size_t)(o0 + j) * (KD_ * H_);
        float ssum = 0.f;
#pragma unroll
        for (int qi = 0; qi < 4; qi++) {
            const float4 wv = *reinterpret_cast<const float4*>(Wr + qi * 128 + lane * 4);
            ssum = fmaf(wv.x, pv[qi].x, fmaf(wv.y, pv[qi].y,
                   fmaf(wv.z, pv[qi].z, fmaf(wv.w, pv[qi].w, ssum))));
        }
        a[j] = warp_sum32(ssum);
    }

    if (lane == 0) {
        const int nb = num[b];
#pragma unroll
        for (int j = 0; j < 4; j++) {
            const int o = o0 + j;
            float vv = a[j] + bias[o] + fmaxf(emb[(size_t)nb * OUT_ + o], 0.f);
            out[(size_t)b * OUT_ + o] = fmaxf(vv, 0.f);
        }
    }
}

// ---------------------------------------------------------------------------
// Launch.  Inputs (metadata order): x, mask, num, queries, W, b, emb
// ---------------------------------------------------------------------------
extern "C" void kernel_launch(void* const* d_in, const int* in_sizes, int n_in,
                              void* d_out, int out_size)
{
    const float* x    = (const float*)d_in[0];
    const int*   mask = (const int*)d_in[1];     // bool -> int32 on upload
    const int*   num  = (const int*)d_in[2];
    const float* q    = (const float*)d_in[3];
    const float* W    = (const float*)d_in[4];
    const float* bias = (const float*)d_in[5];
    const float* emb  = (const float*)d_in[6];
    float*       out  = (float*)d_out;

    pool_pass1<<<NBLK1, 128>>>(x, mask, q);
    pool_combine<<<B_, 512>>>();
    pool_gemv<<<B_ * 8, 256>>>(W, bias, emb, num, out);
}